// round 11
// baseline (speedup 1.0000x reference)
#include <cuda_runtime.h>

// RNN_26895085207932 : Elman RNN, SEQ=2048, B=4096, IN=1, H=32 + Linear(32->1)
// R10: 4 batches per warp (two independent f32x2 streams). Latency-bound fix:
// the per-step serial tail (LDS->fma chain->2x shfl->tanh->STS) now has ILP=2,
// halving per-work stall exposure. Per-SM pipe totals unchanged (grid halves).

typedef unsigned long long ull;

static constexpr int SEQ = 2048;
static constexpr int B   = 4096;
static constexpr int H   = 32;

__device__ __forceinline__ ull pack2(float lo, float hi) {
    ull r; asm("mov.b64 %0, {%1, %2};" : "=l"(r) : "f"(lo), "f"(hi)); return r;
}
__device__ __forceinline__ void unpack2(ull v, float& lo, float& hi) {
    asm("mov.b64 {%0, %1}, %2;" : "=f"(lo), "=f"(hi) : "l"(v));
}
__device__ __forceinline__ ull fma2(ull a, ull b, ull c) {
    ull d; asm("fma.rn.f32x2 %0, %1, %2, %3;" : "=l"(d) : "l"(a), "l"(b), "l"(c)); return d;
}
__device__ __forceinline__ ull add2(ull a, ull b) {
    ull d; asm("add.rn.f32x2 %0, %1, %2;" : "=l"(d) : "l"(a), "l"(b)); return d;
}
__device__ __forceinline__ ull mul2(ull a, ull b) {
    ull d; asm("mul.rn.f32x2 %0, %1, %2;" : "=l"(d) : "l"(a), "l"(b)); return d;
}
__device__ __forceinline__ ull shfl_xor2(ull v, int d) {
    unsigned lo = (unsigned)v, hi = (unsigned)(v >> 32);
    lo = __shfl_xor_sync(0xffffffffu, lo, d);
    hi = __shfl_xor_sync(0xffffffffu, hi, d);
    return ((ull)hi << 32) | (ull)lo;
}
__device__ __forceinline__ float tanh_fast(float z) {
    float r; asm("tanh.approx.f32 %0, %1;" : "=f"(r) : "f"(z)); return r;
}
__device__ __forceinline__ void sts128(ull v0, ull v1, const void* p) {
    asm volatile("st.shared.v2.b64 [%0], {%1, %2};"
                 :: "l"(__cvta_generic_to_shared(p)), "l"(v0), "l"(v1) : "memory");
}

// Skewed hbuf index: unit u lives at u + 2*(u/8) (pad between k-quarters).
__device__ __forceinline__ int skew(int u) { return u + ((u >> 3) << 1); }

__global__ void __launch_bounds__(32, 7)
rnn_kernel(const float* __restrict__ x,      // (SEQ, B, 1)
           const float* __restrict__ hidden, // (1, B, H)
           const float* __restrict__ Wih,    // (H, 1)
           const float* __restrict__ bih,    // (H)
           const float* __restrict__ Whh,    // (H, H)
           const float* __restrict__ bhh,    // (H)
           const float* __restrict__ Wfc,    // (1, H)
           const float* __restrict__ bfc,    // (1)
           float* __restrict__ out)          // (SEQ, B, 1)
{
    // One float4 (= ulonglong2 = 2 packed f32x2) per unit: 4 batches.
    __shared__ __align__(16) ulonglong2 hbuf[H + 6];    // skewed quarters at 0/10/20/30
    __shared__ __align__(16) ulonglong2 phist[32][33];  // wfc*h ring (odd stride pad)

    const int j = threadIdx.x;
    const int q = j >> 3;                // k-quarter this lane reads (0..3)
    const int g = j & 7;                 // quartet group
    const int myu = 4 * g + q;           // unit this lane owns
    const int ub  = 4 * g + (q ^ 1);     // unit of lane j^8
    const int uc  = 4 * g + (q ^ 2);     // unit of lane j^16
    const int ud  = 4 * g + (q ^ 3);     // unit of lane j^24
    const int kofs = 8 * q;

    const int bx = blockIdx.x;           // batch quad
    const int b0 = bx * 4;

    // Weights: rows of the 4 quartet units over MY k-quarter, packed (dup).
    ull wa[8], wb[8], wc[8], wd[8];
#pragma unroll
    for (int k = 0; k < 8; k++) {
        float a = Whh[myu * H + kofs + k];
        float b = Whh[ub  * H + kofs + k];
        float c = Whh[uc  * H + kofs + k];
        float d = Whh[ud  * H + kofs + k];
        wa[k] = pack2(a, a);
        wb[k] = pack2(b, b);
        wc[k] = pack2(c, c);
        wd[k] = pack2(d, d);
    }
    const float wih  = Wih[myu];
    const float bias = bih[myu] + bhh[myu];
    const ull wih2   = pack2(wih, wih);
    const ull bias2  = pack2(bias, bias);
    const float wfc  = Wfc[myu];
    const ull wfc2   = pack2(wfc, wfc);
    const float bfc0 = bfc[0];

    // init h for 4 batches of my unit
    {
        float h0 = hidden[(size_t)(b0 + 0) * H + myu];
        float h1 = hidden[(size_t)(b0 + 1) * H + myu];
        float h2 = hidden[(size_t)(b0 + 2) * H + myu];
        float h3 = hidden[(size_t)(b0 + 3) * H + myu];
        hbuf[skew(myu)] = make_ulonglong2(pack2(h0, h1), pack2(h2, h3));
    }
    __syncwarp();

    const float4* xg = reinterpret_cast<const float4*>(x) + bx;   // step stride B/4
    float4* og       = reinterpret_cast<float4*>(out) + bx;

    const ulonglong2* hq = &hbuf[10 * q];   // my k-quarter (8 units)
    ulonglong2* hw = &hbuf[skew(myu)];

    float4 xpipe[4];
#pragma unroll
    for (int i = 0; i < 4; i++) xpipe[i] = xg[(size_t)i * (B / 4)];
    const float4* xnext = xg + 4 * (size_t)(B / 4);

    for (int base = 0; base < SEQ; base += 32) {
#pragma unroll 2
        for (int qq = 0; qq < 8; qq++) {
            const int s4 = base + qq * 4;
#pragma unroll
            for (int u = 0; u < 4; u++) {
                const int st = s4 + u;
                float4 xs = xpipe[u];
                if (st + 4 < SEQ) xpipe[u] = xnext[(size_t)st * (B / 4)];

                // Two independent streams (batch pairs 01 and 23).
                ull pA0 = fma2(pack2(xs.x, xs.y), wih2, bias2);
                ull pA1 = fma2(pack2(xs.z, xs.w), wih2, bias2);
                ull pB0 = 0, pB1 = 0, pC0 = 0, pC1 = 0, pD0 = 0, pD1 = 0;

                // Matvec over my k-quarter: 8 LDS.128 (one per unit), 8 chains.
#pragma unroll
                for (int k = 0; k < 8; k++) {
                    ulonglong2 hv = hq[k];
                    pA0 = fma2(hv.x, wa[k], pA0);
                    pA1 = fma2(hv.y, wa[k], pA1);
                    pB0 = fma2(hv.x, wb[k], pB0);
                    pB1 = fma2(hv.y, wb[k], pB1);
                    pC0 = fma2(hv.x, wc[k], pC0);
                    pC1 = fma2(hv.y, wc[k], pC1);
                    pD0 = fma2(hv.x, wd[k], pD0);
                    pD1 = fma2(hv.y, wd[k], pD1);
                }

                // Butterfly round 1 (xor 8)
                ull rB0 = shfl_xor2(pB0, 8);
                ull rB1 = shfl_xor2(pB1, 8);
                ull rD0 = shfl_xor2(pD0, 8);
                ull rD1 = shfl_xor2(pD1, 8);
                ull sA0 = add2(pA0, rB0);
                ull sA1 = add2(pA1, rB1);
                ull sC0 = add2(pC0, rD0);
                ull sC1 = add2(pC1, rD1);

                // Round 2 (xor 16)
                ull r20 = shfl_xor2(sC0, 16);
                ull r21 = shfl_xor2(sC1, 16);
                ull z0 = add2(sA0, r20);
                ull z1 = add2(sA1, r21);

                float za, zb, zc, zd;
                unpack2(z0, za, zb);
                unpack2(z1, zc, zd);
                const float h0 = tanh_fast(za);
                const float h1 = tanh_fast(zb);
                const float h2v = tanh_fast(zc);
                const float h3 = tanh_fast(zd);
                const ull hp0 = pack2(h0, h1);
                const ull hp1 = pack2(h2v, h3);

                // Same-warp program-order smem deps; full-mask shfls keep the
                // warp converged each step.
                sts128(hp0, hp1, hw);
                sts128(mul2(hp0, wfc2), mul2(hp1, wfc2), &phist[st & 31][myu]);
            }
        }

        // Transposed output reduction: lane j sums row j (timestep base+j),
        // 4 batches at once.
        {
            const ulonglong2* pr = &phist[j][0];
            ull s00 = 0, s01 = 0, s10 = 0, s11 = 0;
#pragma unroll
            for (int k = 0; k < 16; k++) {
                ulonglong2 a = pr[2 * k];
                ulonglong2 b = pr[2 * k + 1];
                s00 = add2(s00, a.x); s01 = add2(s01, a.y);
                s10 = add2(s10, b.x); s11 = add2(s11, b.y);
            }
            ull sv0 = add2(s00, s10);
            ull sv1 = add2(s01, s11);
            float o0, o1, o2, o3;
            unpack2(sv0, o0, o1);
            unpack2(sv1, o2, o3);
            og[(size_t)(base + j) * (B / 4)] =
                make_float4(o0 + bfc0, o1 + bfc0, o2 + bfc0, o3 + bfc0);
        }
    }
}

extern "C" void kernel_launch(void* const* d_in, const int* in_sizes, int n_in,
                              void* d_out, int out_size) {
    const float* x      = (const float*)d_in[0];
    const float* hidden = (const float*)d_in[1];
    const float* Wih    = (const float*)d_in[2];
    const float* bih    = (const float*)d_in[3];
    const float* Whh    = (const float*)d_in[4];
    const float* bhh    = (const float*)d_in[5];
    const float* Wfc    = (const float*)d_in[6];
    const float* bfc    = (const float*)d_in[7];
    (void)in_sizes; (void)n_in; (void)out_size;

    rnn_kernel<<<B / 4, 32>>>(x, hidden, Wih, bih, Whh, bhh, Wfc, bfc, (float*)d_out);
}

// round 12
// speedup vs baseline: 1.1789x; 1.1789x over previous
#include <cuda_runtime.h>

// RNN_26895085207932 : Elman RNN, SEQ=2048, B=4096, IN=1, H=32 + Linear(32->1)
// R11: revert to R9 structure (2 batches/warp, 2048 warps — R10's 4-batch ILP
// starved the schedulers). Fix the butterfly: the 2-round tree (xor8->add->xor16,
// 56 serial cyc) is replaced by 3 INDEPENDENT bfly shuffles (xor 8/16/24 fetch
// my unit's partials over quarters q^1,q^2,q^3 directly) -> one 26-cyc latency,
// 6 SHFL instead of 8. Also hoist the x-prefetch range check out of the hot loop.

typedef unsigned long long ull;

static constexpr int SEQ = 2048;
static constexpr int B   = 4096;
static constexpr int H   = 32;

__device__ __forceinline__ ull pack2(float lo, float hi) {
    ull r; asm("mov.b64 %0, {%1, %2};" : "=l"(r) : "f"(lo), "f"(hi)); return r;
}
__device__ __forceinline__ void unpack2(ull v, float& lo, float& hi) {
    asm("mov.b64 {%0, %1}, %2;" : "=f"(lo), "=f"(hi) : "l"(v));
}
__device__ __forceinline__ ull fma2(ull a, ull b, ull c) {
    ull d; asm("fma.rn.f32x2 %0, %1, %2, %3;" : "=l"(d) : "l"(a), "l"(b), "l"(c)); return d;
}
__device__ __forceinline__ ull add2(ull a, ull b) {
    ull d; asm("add.rn.f32x2 %0, %1, %2;" : "=l"(d) : "l"(a), "l"(b)); return d;
}
__device__ __forceinline__ ull mul2(ull a, ull b) {
    ull d; asm("mul.rn.f32x2 %0, %1, %2;" : "=l"(d) : "l"(a), "l"(b)); return d;
}
__device__ __forceinline__ ull shfl_xor2(ull v, int d) {
    unsigned lo = (unsigned)v, hi = (unsigned)(v >> 32);
    lo = __shfl_xor_sync(0xffffffffu, lo, d);
    hi = __shfl_xor_sync(0xffffffffu, hi, d);
    return ((ull)hi << 32) | (ull)lo;
}
__device__ __forceinline__ float tanh_fast(float z) {
    float r; asm("tanh.approx.f32 %0, %1;" : "=f"(r) : "f"(z)); return r;
}
__device__ __forceinline__ void sts64(ull v, const void* p) {
    asm volatile("st.shared.b64 [%0], %1;"
                 :: "l"(__cvta_generic_to_shared(p)), "l"(v) : "memory");
}

// Skewed hbuf index: unit u lives at u + 2*(u/8) (16B pad between k-quarters).
__device__ __forceinline__ int skew(int u) { return u + ((u >> 3) << 1); }

// One RNN step. CHECKED guards the x prefetch (only needed in the last block).
#define RNN_STEP(ST, CHECKED)                                                 \
    {                                                                         \
        const int st_ = (ST);                                                 \
        const int u_  = st_ & 3;                                              \
        float2 xs = xpipe[u_];                                                \
        if (!(CHECKED) || (st_ + 4 < SEQ))                                    \
            xpipe[u_] = xnext[(size_t)st_ * (B / 2)];                         \
                                                                              \
        /* 4 independent fma2 chains; chain A seeded with x*W_ih + biases */  \
        ull pA = fma2(pack2(xs.x, xs.y), wih2, bias2);                        \
        ull pB = 0, pC = 0, pD = 0;                                           \
        _Pragma("unroll")                                                     \
        for (int g2 = 0; g2 < 2; g2++) {                                      \
            ulonglong2 h0 = hq[2 * g2];                                       \
            ulonglong2 h1 = hq[2 * g2 + 1];                                   \
            pA = fma2(h0.x, wa[4 * g2],     pA);                              \
            pB = fma2(h0.x, wb[4 * g2],     pB);                              \
            pC = fma2(h0.x, wc[4 * g2],     pC);                              \
            pD = fma2(h0.x, wd[4 * g2],     pD);                              \
            pA = fma2(h0.y, wa[4 * g2 + 1], pA);                              \
            pB = fma2(h0.y, wb[4 * g2 + 1], pB);                              \
            pC = fma2(h0.y, wc[4 * g2 + 1], pC);                              \
            pD = fma2(h0.y, wd[4 * g2 + 1], pD);                              \
            pA = fma2(h1.x, wa[4 * g2 + 2], pA);                              \
            pB = fma2(h1.x, wb[4 * g2 + 2], pB);                              \
            pC = fma2(h1.x, wc[4 * g2 + 2], pC);                              \
            pD = fma2(h1.x, wd[4 * g2 + 2], pD);                              \
            pA = fma2(h1.y, wa[4 * g2 + 3], pA);                              \
            pB = fma2(h1.y, wb[4 * g2 + 3], pB);                              \
            pC = fma2(h1.y, wc[4 * g2 + 3], pC);                              \
            pD = fma2(h1.y, wd[4 * g2 + 3], pD);                              \
        }                                                                     \
                                                                              \
        /* 3 INDEPENDENT bfly shuffles: lane j^8's pB, j^16's pC, j^24's pD   \
           are all my unit's partials over quarters q^1, q^2, q^3. */         \
        ull r1 = shfl_xor2(pB, 8);                                            \
        ull r2 = shfl_xor2(pC, 16);                                           \
        ull r3 = shfl_xor2(pD, 24);                                           \
        ull z  = add2(add2(pA, r1), add2(r2, r3));                            \
                                                                              \
        float zA_, zB_;                                                       \
        unpack2(z, zA_, zB_);                                                 \
        const float hA_ = tanh_fast(zA_);                                     \
        const float hB_ = tanh_fast(zB_);                                     \
        const ull h2_ = pack2(hA_, hB_);                                      \
                                                                              \
        /* Same-warp program-order smem deps; full-mask shfls keep the warp   \
           converged every step. */                                           \
        sts64(h2_, hw);                                                       \
        sts64(mul2(h2_, wfc2), &phist[st_ & 31][myu]);                        \
    }

__global__ void __launch_bounds__(32, 14)
rnn_kernel(const float* __restrict__ x,      // (SEQ, B, 1)
           const float* __restrict__ hidden, // (1, B, H)
           const float* __restrict__ Wih,    // (H, 1)
           const float* __restrict__ bih,    // (H)
           const float* __restrict__ Whh,    // (H, H)
           const float* __restrict__ bhh,    // (H)
           const float* __restrict__ Wfc,    // (1, H)
           const float* __restrict__ bfc,    // (1)
           float* __restrict__ out)          // (SEQ, B, 1)
{
    __shared__ __align__(16) float2 hbuf[H + 6];    // skewed quarters at 0/10/20/30
    __shared__ __align__(16) float2 phist[32][34];  // wfc*h ring (padded rows)

    const int j = threadIdx.x;
    const int q = j >> 3;                // k-quarter this lane reads (0..3)
    const int g = j & 7;                 // quartet group
    const int myu = 4 * g + q;           // unit this lane owns
    const int ub  = 4 * g + (q ^ 1);     // unit of lane j^8
    const int uc  = 4 * g + (q ^ 2);     // unit of lane j^16
    const int ud  = 4 * g + (q ^ 3);     // unit of lane j^24
    const int kofs = 8 * q;              // k-range start (8 wide)

    const int bx = blockIdx.x;           // batch pair
    const int b0 = bx * 2;

    // Weights: rows of the 4 quartet units over MY k-quarter, packed (dup).
    ull wa[8], wb[8], wc[8], wd[8];
#pragma unroll
    for (int k = 0; k < 8; k++) {
        float a = Whh[myu * H + kofs + k];
        float b = Whh[ub  * H + kofs + k];
        float c = Whh[uc  * H + kofs + k];
        float d = Whh[ud  * H + kofs + k];
        wa[k] = pack2(a, a);
        wb[k] = pack2(b, b);
        wc[k] = pack2(c, c);
        wd[k] = pack2(d, d);
    }
    const float wih  = Wih[myu];
    const float bias = bih[myu] + bhh[myu];
    const ull wih2   = pack2(wih, wih);
    const ull bias2  = pack2(bias, bias);
    const float wfc  = Wfc[myu];
    const ull wfc2   = pack2(wfc, wfc);
    const float bfc0 = bfc[0];

    hbuf[skew(myu)] =
        make_float2(hidden[(size_t)b0 * H + myu], hidden[(size_t)(b0 + 1) * H + myu]);
    __syncwarp();  // one-time init ordering

    const float2* xg = reinterpret_cast<const float2*>(x) + bx;   // step stride B/2
    float2* og       = reinterpret_cast<float2*>(out) + bx;

    // My k-quarter: 8 units = 4x LDS.128, base at skewed quarter start (q*10).
    const ulonglong2* hq = reinterpret_cast<const ulonglong2*>(&hbuf[10 * q]);
    float2* hw = &hbuf[skew(myu)];

    float2 xpipe[4];
#pragma unroll
    for (int i = 0; i < 4; i++) xpipe[i] = xg[(size_t)i * (B / 2)];
    const float2* xnext = xg + 4 * (size_t)(B / 2);

    for (int base = 0; base < SEQ; base += 32) {
        if (base + 32 < SEQ) {
            // Hot path: no prefetch range checks anywhere in the block.
#pragma unroll 2
            for (int qq = 0; qq < 8; qq++) {
                const int s4 = base + qq * 4;
                RNN_STEP(s4 + 0, false)
                RNN_STEP(s4 + 1, false)
                RNN_STEP(s4 + 2, false)
                RNN_STEP(s4 + 3, false)
            }
        } else {
            // Last 32-step block: guard the x prefetch.
#pragma unroll 1
            for (int qq = 0; qq < 8; qq++) {
                const int s4 = base + qq * 4;
                RNN_STEP(s4 + 0, true)
                RNN_STEP(s4 + 1, true)
                RNN_STEP(s4 + 2, true)
                RNN_STEP(s4 + 3, true)
            }
        }

        // Transposed output reduction: lane j sums row j (timestep base+j).
        {
            const ulonglong2* pr = reinterpret_cast<const ulonglong2*>(&phist[j][0]);
            ull s0 = 0, s1 = 0, s2 = 0, s3 = 0;
#pragma unroll
            for (int g2 = 0; g2 < 8; g2++) {
                ulonglong2 a = pr[2 * g2];
                ulonglong2 b = pr[2 * g2 + 1];
                s0 = add2(s0, a.x); s1 = add2(s1, a.y);
                s2 = add2(s2, b.x); s3 = add2(s3, b.y);
            }
            ull sv = add2(add2(s0, s1), add2(s2, s3));
            float oA, oB;
            unpack2(sv, oA, oB);
            og[(size_t)(base + j) * (B / 2)] = make_float2(oA + bfc0, oB + bfc0);
        }
    }
}

extern "C" void kernel_launch(void* const* d_in, const int* in_sizes, int n_in,
                              void* d_out, int out_size) {
    const float* x      = (const float*)d_in[0];
    const float* hidden = (const float*)d_in[1];
    const float* Wih    = (const float*)d_in[2];
    const float* bih    = (const float*)d_in[3];
    const float* Whh    = (const float*)d_in[4];
    const float* bhh    = (const float*)d_in[5];
    const float* Wfc    = (const float*)d_in[6];
    const float* bfc    = (const float*)d_in[7];
    (void)in_sizes; (void)n_in; (void)out_size;

    rnn_kernel<<<B / 2, 32>>>(x, hidden, Wih, bih, Whh, bhh, Wfc, bfc, (float*)d_out);
}

// round 13
// speedup vs baseline: 1.2285x; 1.0420x over previous
#include <cuda_runtime.h>

// RNN_26895085207932 : Elman RNN, SEQ=2048, B=4096, IN=1, H=32 + Linear(32->1)
// R12: single-STS step. The h buffer and the wfc*h output ring are merged:
// ring[t&31][u] = s_u * h_t[u]  (s_u = guarded Wfc[u]). The matvec uses
// pre-divided weights w' = Whh/s so w' * (s*h) == Whh*h; the output reduction
// sums ring rows directly. MIO instructions/step: 12 -> 11 (the binding
// resource per the R1..R11 evidence). Ring addressing via running pointers.

typedef unsigned long long ull;

static constexpr int SEQ = 2048;
static constexpr int B   = 4096;
static constexpr int H   = 32;
static constexpr int ROWF2 = 34;             // ring row stride in float2 (2 pad)
static constexpr int ROWB  = ROWF2 * 8;      // 272 bytes; 16B-aligned rows

__device__ __forceinline__ ull pack2(float lo, float hi) {
    ull r; asm("mov.b64 %0, {%1, %2};" : "=l"(r) : "f"(lo), "f"(hi)); return r;
}
__device__ __forceinline__ void unpack2(ull v, float& lo, float& hi) {
    asm("mov.b64 {%0, %1}, %2;" : "=f"(lo), "=f"(hi) : "l"(v));
}
__device__ __forceinline__ ull fma2(ull a, ull b, ull c) {
    ull d; asm("fma.rn.f32x2 %0, %1, %2, %3;" : "=l"(d) : "l"(a), "l"(b), "l"(c)); return d;
}
__device__ __forceinline__ ull add2(ull a, ull b) {
    ull d; asm("add.rn.f32x2 %0, %1, %2;" : "=l"(d) : "l"(a), "l"(b)); return d;
}
__device__ __forceinline__ ull mul2(ull a, ull b) {
    ull d; asm("mul.rn.f32x2 %0, %1, %2;" : "=l"(d) : "l"(a), "l"(b)); return d;
}
__device__ __forceinline__ ull shfl_xor2(ull v, int d) {
    unsigned lo = (unsigned)v, hi = (unsigned)(v >> 32);
    lo = __shfl_xor_sync(0xffffffffu, lo, d);
    hi = __shfl_xor_sync(0xffffffffu, hi, d);
    return ((ull)hi << 32) | (ull)lo;
}
__device__ __forceinline__ float tanh_fast(float z) {
    float r; asm("tanh.approx.f32 %0, %1;" : "=f"(r) : "f"(z)); return r;
}
__device__ __forceinline__ void sts64(ull v, const void* p) {
    asm volatile("st.shared.b64 [%0], %1;"
                 :: "l"(__cvta_generic_to_shared(p)), "l"(v) : "memory");
}
// Guarded output scale: avoid w' = Whh/s blowup; deviation <= 1e-6*|h| in out.
__device__ __forceinline__ float guard_scale(float w) {
    float a = fabsf(w);
    return (a < 1e-6f) ? copysignf(1e-6f, w) : w;
}

// One RNN step. CHECKED guards the x prefetch (only the last 32-block needs it).
#define RNN_STEP(ST, CHECKED)                                                 \
    {                                                                         \
        const int st_ = (ST);                                                 \
        const int u_  = st_ & 3;                                              \
        float2 xs = xpipe[u_];                                                \
        if (!(CHECKED) || (st_ + 4 < SEQ))                                    \
            xpipe[u_] = xnext[(size_t)st_ * (B / 2)];                         \
                                                                              \
        const ulonglong2* hq_ = rdq;                                          \
        ull pA = fma2(pack2(xs.x, xs.y), wih2, bias2);                        \
        ull pB = 0, pC = 0, pD = 0;                                           \
        _Pragma("unroll")                                                     \
        for (int kk = 0; kk < 4; kk++) {                                      \
            ulonglong2 hv = hq_[kk];                                          \
            pA = fma2(hv.x, wa[2 * kk],     pA);                              \
            pB = fma2(hv.x, wb[2 * kk],     pB);                              \
            pC = fma2(hv.x, wc[2 * kk],     pC);                              \
            pD = fma2(hv.x, wd[2 * kk],     pD);                              \
            pA = fma2(hv.y, wa[2 * kk + 1], pA);                              \
            pB = fma2(hv.y, wb[2 * kk + 1], pB);                              \
            pC = fma2(hv.y, wc[2 * kk + 1], pC);                              \
            pD = fma2(hv.y, wd[2 * kk + 1], pD);                              \
        }                                                                     \
                                                                              \
        /* 3 independent bfly shuffles fetch my unit's other 3 k-quarters */  \
        ull r1 = shfl_xor2(pB, 8);                                            \
        ull r2 = shfl_xor2(pC, 16);                                           \
        ull r3 = shfl_xor2(pD, 24);                                           \
        ull z  = add2(add2(pA, r1), add2(r2, r3));                            \
                                                                              \
        float zA_, zB_;                                                       \
        unpack2(z, zA_, zB_);                                                 \
        const ull h2_ = pack2(tanh_fast(zA_), tanh_fast(zB_));                \
                                                                              \
        /* single STS: scaled h serves recurrence AND output reduction */     \
        sts64(mul2(h2_, sfc2), wrp);                                          \
        rdq = reinterpret_cast<const ulonglong2*>(wrp + dqs);                 \
        wrp += ROWB;                                                          \
    }

__global__ void __launch_bounds__(32, 14)
rnn_kernel(const float* __restrict__ x,      // (SEQ, B, 1)
           const float* __restrict__ hidden, // (1, B, H)
           const float* __restrict__ Wih,    // (H, 1)
           const float* __restrict__ bih,    // (H)
           const float* __restrict__ Whh,    // (H, H)
           const float* __restrict__ bhh,    // (H)
           const float* __restrict__ Wfc,    // (1, H)
           const float* __restrict__ bfc,    // (1)
           float* __restrict__ out)          // (SEQ, B, 1)
{
    // ring[r][u] = s_u * h_{base+r}[u] for the current 32-step block.
    __shared__ __align__(16) float2 ring[32][ROWF2];

    const int j = threadIdx.x;
    const int q = j >> 3;                // k-quarter this lane reads (0..3)
    const int g = j & 7;                 // quartet group
    const int myu = 4 * g + q;           // unit this lane owns
    const int ub  = 4 * g + (q ^ 1);     // unit of lane j^8
    const int uc  = 4 * g + (q ^ 2);     // unit of lane j^16
    const int ud  = 4 * g + (q ^ 3);     // unit of lane j^24
    const int kofs = 8 * q;              // k-range start (8 wide)

    const int bx = blockIdx.x;           // batch pair
    const int b0 = bx * 2;

    // Pre-divided weights: w'[u][k] = Whh[u][k] / s_k  (s = guarded Wfc).
    ull wa[8], wb[8], wc[8], wd[8];
#pragma unroll
    for (int k = 0; k < 8; k++) {
        float inv = 1.0f / guard_scale(Wfc[kofs + k]);
        float a = Whh[myu * H + kofs + k] * inv;
        float b = Whh[ub  * H + kofs + k] * inv;
        float c = Whh[uc  * H + kofs + k] * inv;
        float d = Whh[ud  * H + kofs + k] * inv;
        wa[k] = pack2(a, a);
        wb[k] = pack2(b, b);
        wc[k] = pack2(c, c);
        wd[k] = pack2(d, d);
    }
    const float wih  = Wih[myu];
    const float bias = bih[myu] + bhh[myu];
    const ull wih2   = pack2(wih, wih);
    const ull bias2  = pack2(bias, bias);
    const float sfc  = guard_scale(Wfc[myu]);
    const ull sfc2   = pack2(sfc, sfc);
    const float bfc0 = bfc[0];

    // Initial state: row 31 holds s*h_{-1} (step 0 reads it).
    ring[31][myu] = make_float2(sfc * hidden[(size_t)b0 * H + myu],
                                sfc * hidden[(size_t)(b0 + 1) * H + myu]);
    __syncwarp();  // one-time init ordering

    const float2* xg = reinterpret_cast<const float2*>(x) + bx;   // step stride B/2
    float2* og       = reinterpret_cast<float2*>(out) + bx;

    // Running pointers (bytes). dqs: from a step's write slot to the NEXT
    // step's read-quarter base in the same row: (quarter base 8q) - (slot myu).
    const int dqs = (8 * q - myu) * 8;
    char* const ring0 = reinterpret_cast<char*>(&ring[0][0]);
    const ulonglong2* rdq;
    char* wrp;

    float2 xpipe[4];
#pragma unroll
    for (int i = 0; i < 4; i++) xpipe[i] = xg[(size_t)i * (B / 2)];
    const float2* xnext = xg + 4 * (size_t)(B / 2);

    for (int base = 0; base < SEQ; base += 32) {
        // Block-top reset: read row 31 (prev block's last write / init),
        // write row 0.
        rdq = reinterpret_cast<const ulonglong2*>(ring0 + 31 * ROWB + 8 * q * 8);
        wrp = ring0 + myu * 8;

        if (base + 32 < SEQ) {
#pragma unroll 2
            for (int qq = 0; qq < 8; qq++) {
                const int s4 = base + qq * 4;
                RNN_STEP(s4 + 0, false)
                RNN_STEP(s4 + 1, false)
                RNN_STEP(s4 + 2, false)
                RNN_STEP(s4 + 3, false)
            }
        } else {
#pragma unroll 1
            for (int qq = 0; qq < 8; qq++) {
                const int s4 = base + qq * 4;
                RNN_STEP(s4 + 0, true)
                RNN_STEP(s4 + 1, true)
                RNN_STEP(s4 + 2, true)
                RNN_STEP(s4 + 3, true)
            }
        }

        // Output reduction: lane j sums row j (= timestep base+j) directly
        // (ring already holds wfc*h), + bfc.
        {
            const ulonglong2* pr = reinterpret_cast<const ulonglong2*>(&ring[j][0]);
            ull s0 = 0, s1 = 0, s2 = 0, s3 = 0;
#pragma unroll
            for (int g2 = 0; g2 < 8; g2++) {
                ulonglong2 a = pr[2 * g2];
                ulonglong2 b = pr[2 * g2 + 1];
                s0 = add2(s0, a.x); s1 = add2(s1, a.y);
                s2 = add2(s2, b.x); s3 = add2(s3, b.y);
            }
            ull sv = add2(add2(s0, s1), add2(s2, s3));
            float oA, oB;
            unpack2(sv, oA, oB);
            og[(size_t)(base + j) * (B / 2)] = make_float2(oA + bfc0, oB + bfc0);
        }
    }
}

extern "C" void kernel_launch(void* const* d_in, const int* in_sizes, int n_in,
                              void* d_out, int out_size) {
    const float* x      = (const float*)d_in[0];
    const float* hidden = (const float*)d_in[1];
    const float* Wih    = (const float*)d_in[2];
    const float* bih    = (const float*)d_in[3];
    const float* Whh    = (const float*)d_in[4];
    const float* bhh    = (const float*)d_in[5];
    const float* Wfc    = (const float*)d_in[6];
    const float* bfc    = (const float*)d_in[7];
    (void)in_sizes; (void)n_in; (void)out_size;

    rnn_kernel<<<B / 2, 32>>>(x, hidden, Wih, bih, Whh, bhh, Wfc, bfc, (float*)d_out);
}